// round 1
// baseline (speedup 1.0000x reference)
#include <cuda_runtime.h>
#include <cuda_bf16.h>
#include <math.h>

#define BATCH   2
#define SEQ     4096
#define DMODEL  1024
#define DI      2048
#define DS      16
#define DTR     64
#define BL      (BATCH*SEQ)   // 8192

// ---------------- scratch (allocation-free: __device__ globals) ----------------
__device__ float g_xz[(size_t)BL * 2 * DI];   // in_proj output: [8192, 4096] (x_in | z)
__device__ float g_xconv[(size_t)BL * DI];    // conv+silu output
__device__ float g_xdbl[(size_t)BL * 96];     // x_proj output (dt_low | B | C)
__device__ float g_dt[(size_t)BL * DI];       // softplus(dt)
__device__ float g_y[(size_t)BL * DI];        // scan output, gated

enum { EPI_NONE = 0, EPI_BIAS = 1, EPI_BIAS_SOFTPLUS = 2 };

// ---------------- generic fp32 NT GEMM: C[M,N] = A[M,K] * W[N,K]^T (+bias)(+softplus)
// A row stride = lda. 128x128 tile, BK=16, 256 threads, 8x8 per thread.
template<int EPI>
__global__ __launch_bounds__(256) void sgemm_nt(
    const float* __restrict__ A, const float* __restrict__ W,
    const float* __restrict__ bias, float* __restrict__ C,
    int M, int N, int K, int lda)
{
    __shared__ float As[16][132];
    __shared__ float Bs[16][132];

    const int tid = threadIdx.x;
    const int bm  = blockIdx.y * 128;
    const int bn  = blockIdx.x * 128;
    const int tx  = tid & 15;
    const int ty  = tid >> 4;

    const int ksteps = K / gridDim.z;
    const int kbeg   = blockIdx.z * ksteps;
    const int kend   = kbeg + ksteps;

    float acc[8][8];
    #pragma unroll
    for (int i = 0; i < 8; i++)
        #pragma unroll
        for (int j = 0; j < 8; j++) acc[i][j] = 0.f;

    for (int kt = kbeg; kt < kend; kt += 16) {
        // load 128x16 A-tile and 128x16 W-tile (both K-contiguous), transposed into smem
        #pragma unroll
        for (int it = 0; it < 2; it++) {
            int idx  = tid + it * 256;      // 0..511
            int row  = idx >> 2;            // 0..127
            int k4   = (idx & 3) << 2;      // 0,4,8,12
            float4 va = *(const float4*)&A[(size_t)(bm + row) * lda + kt + k4];
            As[k4 + 0][row] = va.x; As[k4 + 1][row] = va.y;
            As[k4 + 2][row] = va.z; As[k4 + 3][row] = va.w;
            int wrow = bn + row;
            float4 vb = make_float4(0.f, 0.f, 0.f, 0.f);
            if (wrow < N) vb = *(const float4*)&W[(size_t)wrow * K + kt + k4];
            Bs[k4 + 0][row] = vb.x; Bs[k4 + 1][row] = vb.y;
            Bs[k4 + 2][row] = vb.z; Bs[k4 + 3][row] = vb.w;
        }
        __syncthreads();

        #pragma unroll
        for (int k = 0; k < 16; k++) {
            float a[8], b[8];
            float4 a0 = *(const float4*)&As[k][ty * 4];
            float4 a1 = *(const float4*)&As[k][64 + ty * 4];
            float4 b0 = *(const float4*)&Bs[k][tx * 4];
            float4 b1 = *(const float4*)&Bs[k][64 + tx * 4];
            a[0]=a0.x; a[1]=a0.y; a[2]=a0.z; a[3]=a0.w;
            a[4]=a1.x; a[5]=a1.y; a[6]=a1.z; a[7]=a1.w;
            b[0]=b0.x; b[1]=b0.y; b[2]=b0.z; b[3]=b0.w;
            b[4]=b1.x; b[5]=b1.y; b[6]=b1.z; b[7]=b1.w;
            #pragma unroll
            for (int i = 0; i < 8; i++)
                #pragma unroll
                for (int j = 0; j < 8; j++)
                    acc[i][j] = fmaf(a[i], b[j], acc[i][j]);
        }
        __syncthreads();
    }

    // epilogue
    #pragma unroll
    for (int i = 0; i < 8; i++) {
        int r = bm + ((i < 4) ? (ty * 4 + i) : (64 + ty * 4 + i - 4));
        #pragma unroll
        for (int j = 0; j < 8; j++) {
            int c = bn + ((j < 4) ? (tx * 4 + j) : (64 + tx * 4 + j - 4));
            if (c < N) {
                float v = acc[i][j];
                if (gridDim.z > 1) {
                    atomicAdd(&C[(size_t)r * N + c], v);
                } else {
                    if (EPI >= EPI_BIAS) v += bias[c];
                    if (EPI == EPI_BIAS_SOFTPLUS)
                        v = fmaxf(v, 0.f) + log1pf(expf(-fabsf(v)));
                    C[(size_t)r * N + c] = v;
                }
            }
        }
    }
}

// ---------------- depthwise causal conv (width 4) + SiLU ----------------
__global__ __launch_bounds__(256) void conv_silu_kernel(
    const float* __restrict__ xz, const float* __restrict__ cw,
    const float* __restrict__ cb, float* __restrict__ xc)
{
    int idx = blockIdx.x * 256 + threadIdx.x;       // over BL*DI
    int d   = idx & (DI - 1);
    int row = idx >> 11;                            // b*SEQ + t
    int t   = row & (SEQ - 1);

    float s = cb[d];
    #pragma unroll
    for (int k = 0; k < 4; k++) {
        int tp = t + k - 3;
        if (tp >= 0)
            s = fmaf(xz[(size_t)(row + k - 3) * (2 * DI) + d], cw[d * 4 + k], s);
    }
    // silu
    float sig = 1.f / (1.f + __expf(-s));
    xc[(size_t)idx] = s * sig;
}

// ---------------- selective scan: 1 warp = 2 channels x 16 states ----------------
__global__ __launch_bounds__(256) void scan_kernel(
    const float* __restrict__ xc, const float* __restrict__ dtv,
    const float* __restrict__ xdbl, const float* __restrict__ A_log,
    const float* __restrict__ Dp, const float* __restrict__ xz,
    float* __restrict__ y)
{
    int w    = (blockIdx.x * blockDim.x + threadIdx.x) >> 5;  // 0..2047
    int lane = threadIdx.x & 31;
    int b    = w >> 10;                 // batch
    int dp   = w & 1023;
    int s    = lane & 15;               // state index
    int d    = dp * 2 + (lane >> 4);    // channel

    float Ai   = -__expf(A_log[s * DI + d]);
    float sA   = (fabsf(Ai) < 1e-6f) ? 1.f : Ai;
    float invA = 1.f / sA;
    float Dd   = Dp[d];

    const float* xc_p = xc   + (size_t)b * SEQ * DI + d;
    const float* dt_p = dtv  + (size_t)b * SEQ * DI + d;
    const float* bc_p = xdbl + (size_t)b * SEQ * 96 + DTR + s;
    const float* z_p  = xz   + (size_t)b * SEQ * (2 * DI) + DI + d;
    float*       y_p  = y    + (size_t)b * SEQ * DI + d;

    float h = 0.f;
    for (int t = 0; t < SEQ; t++) {
        float xv  = xc_p[(size_t)t * DI];
        float dtt = dt_p[(size_t)t * DI];
        float Bv  = bc_p[(size_t)t * 96];
        float Cv  = bc_p[(size_t)t * 96 + DS];

        float a   = __expf(dtt * Ai);
        float bb  = (a - 1.f) * invA * Bv;
        h = fmaf(a, h, bb * xv);
        float p = h * Cv;
        p += __shfl_xor_sync(0xffffffffu, p, 8);
        p += __shfl_xor_sync(0xffffffffu, p, 4);
        p += __shfl_xor_sync(0xffffffffu, p, 2);
        p += __shfl_xor_sync(0xffffffffu, p, 1);
        if (s == 0) {
            float yv  = p + Dd * xv;
            float zv  = z_p[(size_t)t * (2 * DI)];
            float sig = 1.f / (1.f + __expf(-zv));
            y_p[(size_t)t * DI] = yv * (zv * sig);
        }
    }
}

// ---------------- launch ----------------
extern "C" void kernel_launch(void* const* d_in, const int* in_sizes, int n_in,
                              void* d_out, int out_size)
{
    const float* x          = (const float*)d_in[0];
    const float* in_proj_w  = (const float*)d_in[1];
    const float* in_proj_b  = (const float*)d_in[2];
    const float* conv_w     = (const float*)d_in[3];
    const float* conv_b     = (const float*)d_in[4];
    const float* A_log      = (const float*)d_in[5];
    const float* Dp         = (const float*)d_in[6];
    const float* x_proj_w   = (const float*)d_in[7];
    const float* dt_proj_w  = (const float*)d_in[8];
    const float* dt_proj_b  = (const float*)d_in[9];
    const float* out_proj_w = (const float*)d_in[10];
    const float* out_proj_b = (const float*)d_in[11];
    float* out = (float*)d_out;

    float *xz, *xconv, *xdbl, *dt, *y;
    cudaGetSymbolAddress((void**)&xz,    g_xz);
    cudaGetSymbolAddress((void**)&xconv, g_xconv);
    cudaGetSymbolAddress((void**)&xdbl,  g_xdbl);
    cudaGetSymbolAddress((void**)&dt,    g_dt);
    cudaGetSymbolAddress((void**)&y,     g_y);

    dim3 blk(256);

    // G1: xz = x @ in_proj_w^T + b   [8192, 4096], K=1024
    sgemm_nt<EPI_BIAS><<<dim3(4096 / 128, BL / 128, 1), blk>>>(
        x, in_proj_w, in_proj_b, xz, BL, 2 * DI, DMODEL, DMODEL);

    // conv + silu over x_in half of xz
    conv_silu_kernel<<<(BL * DI) / 256, blk>>>(xz, conv_w, conv_b, xconv);

    // G2: x_dbl = x_conv @ x_proj_w^T   [8192, 96], K=2048
    sgemm_nt<EPI_NONE><<<dim3(1, BL / 128, 1), blk>>>(
        xconv, x_proj_w, nullptr, xdbl, BL, DTR + 2 * DS, DI, DI);

    // G3: dt = softplus(dt_low @ dt_proj_w^T + dt_proj_b)   [8192, 2048], K=64, lda=96
    sgemm_nt<EPI_BIAS_SOFTPLUS><<<dim3(DI / 128, BL / 128, 1), blk>>>(
        xdbl, dt_proj_w, dt_proj_b, dt, BL, DI, DTR, DTR + 2 * DS);

    // selective scan + gating (fused silu(z) multiply)
    scan_kernel<<<(BATCH * (DI / 2) * 32) / 256, blk>>>(
        xconv, dt, xdbl, A_log, Dp, xz, y);

    // G5: out = y @ out_proj_w^T + b   [8192, 1024], K=2048
    sgemm_nt<EPI_BIAS><<<dim3(DMODEL / 128, BL / 128, 1), blk>>>(
        y, out_proj_w, out_proj_b, out, BL, DMODEL, DI, DI);
}

// round 3
// speedup vs baseline: 1.2982x; 1.2982x over previous
#include <cuda_runtime.h>
#include <cuda_bf16.h>
#include <math.h>
#include <stdint.h>

#define BATCH   2
#define SEQ     4096
#define DMODEL  1024
#define DI      2048
#define DS      16
#define DTR     64
#define BL      (BATCH*SEQ)   // 8192

// ---------------- scratch (allocation-free: __device__ globals) ----------------
__device__ float g_xz[(size_t)BL * 2 * DI];
__device__ float g_xconv[(size_t)BL * DI];
__device__ float g_xdbl[(size_t)BL * 96];
__device__ float g_dt[(size_t)BL * DI];
__device__ float g_y[(size_t)BL * DI];

__device__ __nv_bfloat16 g_xhi[(size_t)BL * DMODEL];
__device__ __nv_bfloat16 g_xlo[(size_t)BL * DMODEL];
__device__ __nv_bfloat16 g_w1hi[(size_t)2 * DI * DMODEL];
__device__ __nv_bfloat16 g_w1lo[(size_t)2 * DI * DMODEL];
__device__ __nv_bfloat16 g_yhi[(size_t)BL * DI];
__device__ __nv_bfloat16 g_ylo[(size_t)BL * DI];
__device__ __nv_bfloat16 g_w5hi[(size_t)DMODEL * DI];
__device__ __nv_bfloat16 g_w5lo[(size_t)DMODEL * DI];

enum { EPI_NONE = 0, EPI_BIAS = 1, EPI_BIAS_SOFTPLUS = 2 };

// =================== helpers ===================
__device__ __forceinline__ uint32_t smem_u32(const void* p) {
    uint32_t a;
    asm("{ .reg .u64 t; cvta.to.shared.u64 t, %1; cvt.u32.u64 %0, t; }" : "=r"(a) : "l"(p));
    return a;
}
__device__ __forceinline__ void cp16(uint32_t s, const void* g) {
    asm volatile("cp.async.cg.shared.global [%0], [%1], 16;" :: "r"(s), "l"(g) : "memory");
}
__device__ __forceinline__ void ldsm_x4(uint32_t addr, uint32_t* r) {
    asm volatile("ldmatrix.sync.aligned.m8n8.x4.shared.b16 {%0,%1,%2,%3}, [%4];"
                 : "=r"(r[0]), "=r"(r[1]), "=r"(r[2]), "=r"(r[3]) : "r"(addr));
}
__device__ __forceinline__ void mma_bf16(float* c, const uint32_t* a, const uint32_t* b) {
    asm volatile(
        "mma.sync.aligned.m16n8k16.row.col.f32.bf16.bf16.f32 "
        "{%0,%1,%2,%3}, {%4,%5,%6,%7}, {%8,%9}, {%0,%1,%2,%3};"
        : "+f"(c[0]), "+f"(c[1]), "+f"(c[2]), "+f"(c[3])
        : "r"(a[0]), "r"(a[1]), "r"(a[2]), "r"(a[3]), "r"(b[0]), "r"(b[1]));
}

// =================== mma.sync bf16-split GEMM ===================
// C[M,N] = (Ahi+Alo)[M,K] @ (Bhi+Blo)[N,K]^T + bias, fp32 accumulators.
// Products kept: hi*hi + hi*lo + lo*hi.
// CTA: 128x128 tile, BK=32, 256 threads (8 warps of 64x32), double-buffered cp.async.
// smem tile rows padded to 80B (40 bf16) -> conflict-free ldmatrix.
#define TSTRIDE 80
#define TILE_B  (128 * TSTRIDE)          // 10240 bytes per operand tile
#define STAGE_B (4 * TILE_B)             // 40960 bytes per stage

__global__ __launch_bounds__(256) void gemm_mma(
    const __nv_bfloat16* __restrict__ Ahi, const __nv_bfloat16* __restrict__ Alo,
    const __nv_bfloat16* __restrict__ Bhi, const __nv_bfloat16* __restrict__ Blo,
    const float* __restrict__ bias, float* __restrict__ C,
    int M, int N, int K)
{
    extern __shared__ char smem[];
    const uint32_t sb = smem_u32(smem);
    const int tid  = threadIdx.x;
    const int wid  = tid >> 5;
    const int lane = tid & 31;
    const int bm   = blockIdx.y * 128;
    const int bn   = blockIdx.x * 128;
    const int wm   = (wid & 1) * 64;     // warp row offset in tile
    const int wn   = (wid >> 1) * 32;    // warp col offset in tile

    const size_t kb = (size_t)K * 2;     // row bytes
    const char* src[4] = {
        (const char*)Ahi + (size_t)bm * kb,
        (const char*)Alo + (size_t)bm * kb,
        (const char*)Bhi + (size_t)bn * kb,
        (const char*)Blo + (size_t)bn * kb };

    const int nch = K >> 5;              // chunks of 32

    float acc[4][4][4];
    #pragma unroll
    for (int i = 0; i < 4; i++)
        #pragma unroll
        for (int j = 0; j < 4; j++)
            #pragma unroll
            for (int v = 0; v < 4; v++) acc[i][j][v] = 0.f;

    // load chunk i (32 k-cols = 64 bytes/row) into stage i&1
    auto load_chunk = [&](int i) {
        const uint32_t st = sb + (uint32_t)(i & 1) * STAGE_B;
        const size_t ko = (size_t)i * 64;
        #pragma unroll
        for (int j = 0; j < 8; j++) {
            int idx = j * 256 + tid;           // 0..2047
            int m   = idx >> 9;                // operand tile 0..3
            int r   = (idx & 511) >> 2;        // row 0..127
            int c   = idx & 3;                 // 16B chunk 0..3
            cp16(st + (uint32_t)m * TILE_B + (uint32_t)(r * TSTRIDE + c * 16),
                 src[m] + (size_t)r * kb + ko + c * 16);
        }
        asm volatile("cp.async.commit_group;" ::: "memory");
    };

    // per-warp ldmatrix base offsets (within a stage)
    const uint32_t a_off = (uint32_t)((wm + (lane & 15)) * TSTRIDE + ((lane >> 4) << 4));
    const uint32_t b_off = (uint32_t)((wn + (lane & 7) + ((lane >> 4) << 3)) * TSTRIDE
                                      + (((lane >> 3) & 1) << 4));

    load_chunk(0);

    for (int i = 0; i < nch; i++) {
        if (i + 1 < nch) {
            load_chunk(i + 1);
            asm volatile("cp.async.wait_group 1;" ::: "memory");
        } else {
            asm volatile("cp.async.wait_group 0;" ::: "memory");
        }
        __syncthreads();

        const uint32_t st = sb + (uint32_t)(i & 1) * STAGE_B;
        #pragma unroll
        for (int kk = 0; kk < 2; kk++) {
            const uint32_t kby = (uint32_t)kk * 32;
            uint32_t ah[4][4], al[4][4];
            #pragma unroll
            for (int mi = 0; mi < 4; mi++) {
                uint32_t ao = a_off + (uint32_t)(mi * 16 * TSTRIDE) + kby;
                ldsm_x4(st + ao, ah[mi]);
                ldsm_x4(st + TILE_B + ao, al[mi]);
            }
            uint32_t bh[2][4], bl[2][4];
            #pragma unroll
            for (int np = 0; np < 2; np++) {
                uint32_t bo = b_off + (uint32_t)(np * 16 * TSTRIDE) + kby;
                ldsm_x4(st + 2 * TILE_B + bo, bh[np]);
                ldsm_x4(st + 3 * TILE_B + bo, bl[np]);
            }
            #pragma unroll
            for (int mi = 0; mi < 4; mi++)
                #pragma unroll
                for (int ni = 0; ni < 4; ni++) {
                    const uint32_t* ph = &bh[ni >> 1][(ni & 1) * 2];
                    const uint32_t* pl = &bl[ni >> 1][(ni & 1) * 2];
                    mma_bf16(acc[mi][ni], ah[mi], ph);
                    mma_bf16(acc[mi][ni], ah[mi], pl);
                    mma_bf16(acc[mi][ni], al[mi], ph);
                }
        }
        __syncthreads();
    }

    // epilogue
    #pragma unroll
    for (int mi = 0; mi < 4; mi++) {
        int r0 = bm + wm + mi * 16 + (lane >> 2);
        #pragma unroll
        for (int ni = 0; ni < 4; ni++) {
            int c = bn + wn + ni * 8 + (lane & 3) * 2;
            float2 bi = *(const float2*)&bias[c];
            float2 v0 = make_float2(acc[mi][ni][0] + bi.x, acc[mi][ni][1] + bi.y);
            float2 v1 = make_float2(acc[mi][ni][2] + bi.x, acc[mi][ni][3] + bi.y);
            *(float2*)&C[(size_t)r0 * N + c]       = v0;
            *(float2*)&C[(size_t)(r0 + 8) * N + c] = v1;
        }
    }
}

// =================== fp32 -> bf16 hi/lo split ===================
__global__ __launch_bounds__(256) void split_kernel(
    const float* __restrict__ src, __nv_bfloat16* __restrict__ hi,
    __nv_bfloat16* __restrict__ lo, int n)
{
    int i = blockIdx.x * 256 + threadIdx.x;
    if (i >= n) return;
    float v = src[i];
    __nv_bfloat16 h = __float2bfloat16(v);
    float r = v - __bfloat162float(h);
    hi[i] = h;
    lo[i] = __float2bfloat16(r);
}

// ---------------- generic fp32 NT GEMM (small GEMMs) ----------------
template<int EPI>
__global__ __launch_bounds__(256) void sgemm_nt(
    const float* __restrict__ A, const float* __restrict__ W,
    const float* __restrict__ bias, float* __restrict__ C,
    int M, int N, int K, int lda)
{
    __shared__ float As[16][132];
    __shared__ float Bs[16][132];

    const int tid = threadIdx.x;
    const int bm  = blockIdx.y * 128;
    const int bn  = blockIdx.x * 128;
    const int tx  = tid & 15;
    const int ty  = tid >> 4;

    const int ksteps = K / gridDim.z;
    const int kbeg   = blockIdx.z * ksteps;
    const int kend   = kbeg + ksteps;

    float acc[8][8];
    #pragma unroll
    for (int i = 0; i < 8; i++)
        #pragma unroll
        for (int j = 0; j < 8; j++) acc[i][j] = 0.f;

    for (int kt = kbeg; kt < kend; kt += 16) {
        #pragma unroll
        for (int it = 0; it < 2; it++) {
            int idx  = tid + it * 256;
            int row  = idx >> 2;
            int k4   = (idx & 3) << 2;
            float4 va = *(const float4*)&A[(size_t)(bm + row) * lda + kt + k4];
            As[k4 + 0][row] = va.x; As[k4 + 1][row] = va.y;
            As[k4 + 2][row] = va.z; As[k4 + 3][row] = va.w;
            int wrow = bn + row;
            float4 vb = make_float4(0.f, 0.f, 0.f, 0.f);
            if (wrow < N) vb = *(const float4*)&W[(size_t)wrow * K + kt + k4];
            Bs[k4 + 0][row] = vb.x; Bs[k4 + 1][row] = vb.y;
            Bs[k4 + 2][row] = vb.z; Bs[k4 + 3][row] = vb.w;
        }
        __syncthreads();

        #pragma unroll
        for (int k = 0; k < 16; k++) {
            float a[8], b[8];
            float4 a0 = *(const float4*)&As[k][ty * 4];
            float4 a1 = *(const float4*)&As[k][64 + ty * 4];
            float4 b0 = *(const float4*)&Bs[k][tx * 4];
            float4 b1 = *(const float4*)&Bs[k][64 + tx * 4];
            a[0]=a0.x; a[1]=a0.y; a[2]=a0.z; a[3]=a0.w;
            a[4]=a1.x; a[5]=a1.y; a[6]=a1.z; a[7]=a1.w;
            b[0]=b0.x; b[1]=b0.y; b[2]=b0.z; b[3]=b0.w;
            b[4]=b1.x; b[5]=b1.y; b[6]=b1.z; b[7]=b1.w;
            #pragma unroll
            for (int i = 0; i < 8; i++)
                #pragma unroll
                for (int j = 0; j < 8; j++)
                    acc[i][j] = fmaf(a[i], b[j], acc[i][j]);
        }
        __syncthreads();
    }

    #pragma unroll
    for (int i = 0; i < 8; i++) {
        int r = bm + ((i < 4) ? (ty * 4 + i) : (64 + ty * 4 + i - 4));
        #pragma unroll
        for (int j = 0; j < 8; j++) {
            int c = bn + ((j < 4) ? (tx * 4 + j) : (64 + tx * 4 + j - 4));
            if (c < N) {
                float v = acc[i][j];
                if (gridDim.z > 1) {
                    atomicAdd(&C[(size_t)r * N + c], v);
                } else {
                    if (EPI >= EPI_BIAS) v += bias[c];
                    if (EPI == EPI_BIAS_SOFTPLUS)
                        v = fmaxf(v, 0.f) + log1pf(expf(-fabsf(v)));
                    C[(size_t)r * N + c] = v;
                }
            }
        }
    }
}

// ---------------- depthwise causal conv (width 4) + SiLU ----------------
__global__ __launch_bounds__(256) void conv_silu_kernel(
    const float* __restrict__ xz, const float* __restrict__ cw,
    const float* __restrict__ cb, float* __restrict__ xc)
{
    int idx = blockIdx.x * 256 + threadIdx.x;
    int d   = idx & (DI - 1);
    int row = idx >> 11;
    int t   = row & (SEQ - 1);

    float s = cb[d];
    #pragma unroll
    for (int k = 0; k < 4; k++) {
        int tp = t + k - 3;
        if (tp >= 0)
            s = fmaf(xz[(size_t)(row + k - 3) * (2 * DI) + d], cw[d * 4 + k], s);
    }
    float sig = 1.f / (1.f + __expf(-s));
    xc[(size_t)idx] = s * sig;
}

// ---------------- selective scan: 1 warp = 2 channels x 16 states ----------------
__global__ __launch_bounds__(256) void scan_kernel(
    const float* __restrict__ xc, const float* __restrict__ dtv,
    const float* __restrict__ xdbl, const float* __restrict__ A_log,
    const float* __restrict__ Dp, const float* __restrict__ xz,
    float* __restrict__ y)
{
    int w    = (blockIdx.x * blockDim.x + threadIdx.x) >> 5;
    int lane = threadIdx.x & 31;
    int b    = w >> 10;
    int dp   = w & 1023;
    int s    = lane & 15;
    int d    = dp * 2 + (lane >> 4);

    float Ai   = -__expf(A_log[s * DI + d]);
    float sA   = (fabsf(Ai) < 1e-6f) ? 1.f : Ai;
    float invA = 1.f / sA;
    float Dd   = Dp[d];

    const float* xc_p = xc   + (size_t)b * SEQ * DI + d;
    const float* dt_p = dtv  + (size_t)b * SEQ * DI + d;
    const float* bc_p = xdbl + (size_t)b * SEQ * 96 + DTR + s;
    const float* z_p  = xz   + (size_t)b * SEQ * (2 * DI) + DI + d;
    float*       y_p  = y    + (size_t)b * SEQ * DI + d;

    float h = 0.f;
    for (int t = 0; t < SEQ; t++) {
        float xv  = xc_p[(size_t)t * DI];
        float dtt = dt_p[(size_t)t * DI];
        float Bv  = bc_p[(size_t)t * 96];
        float Cv  = bc_p[(size_t)t * 96 + DS];

        float a   = __expf(dtt * Ai);
        float bb  = (a - 1.f) * invA * Bv;
        h = fmaf(a, h, bb * xv);
        float p = h * Cv;
        p += __shfl_xor_sync(0xffffffffu, p, 8);
        p += __shfl_xor_sync(0xffffffffu, p, 4);
        p += __shfl_xor_sync(0xffffffffu, p, 2);
        p += __shfl_xor_sync(0xffffffffu, p, 1);
        if (s == 0) {
            float yv  = p + Dd * xv;
            float zv  = z_p[(size_t)t * (2 * DI)];
            float sig = 1.f / (1.f + __expf(-zv));
            y_p[(size_t)t * DI] = yv * (zv * sig);
        }
    }
}

// ---------------- launch ----------------
extern "C" void kernel_launch(void* const* d_in, const int* in_sizes, int n_in,
                              void* d_out, int out_size)
{
    const float* x          = (const float*)d_in[0];
    const float* in_proj_w  = (const float*)d_in[1];
    const float* in_proj_b  = (const float*)d_in[2];
    const float* conv_w     = (const float*)d_in[3];
    const float* conv_b     = (const float*)d_in[4];
    const float* A_log      = (const float*)d_in[5];
    const float* Dp         = (const float*)d_in[6];
    const float* x_proj_w   = (const float*)d_in[7];
    const float* dt_proj_w  = (const float*)d_in[8];
    const float* dt_proj_b  = (const float*)d_in[9];
    const float* out_proj_w = (const float*)d_in[10];
    const float* out_proj_b = (const float*)d_in[11];
    float* out = (float*)d_out;

    float *xz, *xconv, *xdbl, *dt, *y;
    cudaGetSymbolAddress((void**)&xz,    g_xz);
    cudaGetSymbolAddress((void**)&xconv, g_xconv);
    cudaGetSymbolAddress((void**)&xdbl,  g_xdbl);
    cudaGetSymbolAddress((void**)&dt,    g_dt);
    cudaGetSymbolAddress((void**)&y,     g_y);

    __nv_bfloat16 *xhi, *xlo, *w1hi, *w1lo, *yhi, *ylo, *w5hi, *w5lo;
    cudaGetSymbolAddress((void**)&xhi,  g_xhi);
    cudaGetSymbolAddress((void**)&xlo,  g_xlo);
    cudaGetSymbolAddress((void**)&w1hi, g_w1hi);
    cudaGetSymbolAddress((void**)&w1lo, g_w1lo);
    cudaGetSymbolAddress((void**)&yhi,  g_yhi);
    cudaGetSymbolAddress((void**)&ylo,  g_ylo);
    cudaGetSymbolAddress((void**)&w5hi, g_w5hi);
    cudaGetSymbolAddress((void**)&w5lo, g_w5lo);

    const int SMEM_MMA = 2 * STAGE_B;   // 81920
    cudaFuncSetAttribute(gemm_mma, cudaFuncAttributeMaxDynamicSharedMemorySize, SMEM_MMA);

    dim3 blk(256);

    // split inputs for G1
    {
        int n1 = BL * DMODEL;
        split_kernel<<<(n1 + 255) / 256, blk>>>(x, xhi, xlo, n1);
        int n2 = 2 * DI * DMODEL;
        split_kernel<<<(n2 + 255) / 256, blk>>>(in_proj_w, w1hi, w1lo, n2);
    }

    // G1 (tensor): xz = x @ in_proj_w^T + b   [8192, 4096], K=1024
    gemm_mma<<<dim3(2 * DI / 128, BL / 128), blk, SMEM_MMA>>>(
        xhi, xlo, w1hi, w1lo, in_proj_b, xz, BL, 2 * DI, DMODEL);

    // conv + silu over x_in half of xz
    conv_silu_kernel<<<(BL * DI) / 256, blk>>>(xz, conv_w, conv_b, xconv);

    // G2: x_dbl = x_conv @ x_proj_w^T   [8192, 96], K=2048, split-K x4
    cudaMemsetAsync(xdbl, 0, (size_t)BL * 96 * sizeof(float));
    sgemm_nt<EPI_NONE><<<dim3(1, BL / 128, 4), blk>>>(
        xconv, x_proj_w, nullptr, xdbl, BL, DTR + 2 * DS, DI, DI);

    // G3: dt = softplus(dt_low @ dt_proj_w^T + dt_proj_b)   [8192, 2048], K=64
    sgemm_nt<EPI_BIAS_SOFTPLUS><<<dim3(DI / 128, BL / 128, 1), blk>>>(
        xdbl, dt_proj_w, dt_proj_b, dt, BL, DI, DTR, DTR + 2 * DS);

    // selective scan + gating
    scan_kernel<<<(BATCH * (DI / 2) * 32) / 256, blk>>>(
        xconv, dt, xdbl, A_log, Dp, xz, y);

    // split y and out_proj_w for G5
    {
        int n1 = BL * DI;
        split_kernel<<<(n1 + 255) / 256, blk>>>(y, yhi, ylo, n1);
        int n2 = DMODEL * DI;
        split_kernel<<<(n2 + 255) / 256, blk>>>(out_proj_w, w5hi, w5lo, n2);
    }

    // G5 (tensor): out = y @ out_proj_w^T + b   [8192, 1024], K=2048
    gemm_mma<<<dim3(DMODEL / 128, BL / 128), blk, SMEM_MMA>>>(
        yhi, ylo, w5hi, w5lo, out_proj_b, out, BL, DMODEL, DI);
}